// round 1
// baseline (speedup 1.0000x reference)
#include <cuda_runtime.h>
#include <cstdint>

// Problem constants
#define J   17
#define E   4096
#define M16 16          // number of bones
#define K1  (2*E)       // 8192
#define K2  E           // 4096
#define TILE_K 256
#define KS1 (K1/TILE_K) // 32
#define KS2 (K2/TILE_K) // 16
#define NTILES (E/512)  // 8 (256 threads * 2 cols)
#define LN_EPS 1e-5f

// -------- device scratch (no allocations allowed) --------
__device__ unsigned long long d_pair_dup[K1 * M16];   // 1 MB: {p,p} per (k,m)
__device__ unsigned long long d_h_dup  [K2 * M16];    // 512 KB
__device__ float d_partial[KS1 * M16 * E];            // 8 MB, reused by GEMM2

// -------- helpers --------
__device__ __forceinline__ void fma2(unsigned long long& d,
                                     unsigned long long a,
                                     unsigned long long b) {
    asm("fma.rn.f32x2 %0, %1, %2, %0;" : "+l"(d) : "l"(a), "l"(b));
}

__device__ __forceinline__ unsigned long long dup_pack(float p) {
    unsigned int u = __float_as_uint(p);
    return ((unsigned long long)u << 32) | (unsigned long long)u;
}

// ============================================================
// Kernel 1: L2-normalize joint embeddings, scale by sqrt(E)=64.
// grid=17, block=256. Writes joint part of output.
// ============================================================
__global__ void __launch_bounds__(256) normalize_kernel(
    const float* __restrict__ x, float* __restrict__ out_joint)
{
    int row = blockIdx.x;
    int tid = threadIdx.x;
    const float* xr = x + (size_t)row * E;

    float s = 0.f;
    #pragma unroll
    for (int i = 0; i < E / 256; i++) {
        float v = xr[tid + i * 256];
        s += v * v;
    }
    __shared__ float red[256];
    red[tid] = s;
    __syncthreads();
    for (int off = 128; off > 0; off >>= 1) {
        if (tid < off) red[tid] += red[tid + off];
        __syncthreads();
    }
    __shared__ float s_inv;
    if (tid == 0) {
        float nrm = sqrtf(red[0]);
        s_inv = 64.0f / fmaxf(nrm, 1e-12f);
    }
    __syncthreads();
    float inv = s_inv;
    #pragma unroll
    for (int i = 0; i < E / 256; i++) {
        int n = tid + i * 256;
        out_joint[(size_t)row * E + n] = xr[n] * inv;
    }
}

// ============================================================
// Kernel 2: build duplicated pair activations, [K1][16] of {p,p}
// pair[m][k] = joint[bp[m][k<E?0:1]][k % E]
// ============================================================
__global__ void __launch_bounds__(256) pair_dup_kernel(
    const float* __restrict__ joint, const int* __restrict__ bp)
{
    int idx = blockIdx.x * 256 + threadIdx.x;   // idx = k*16 + m
    int k = idx >> 4;
    int m = idx & 15;
    int side = (k >= E) ? 1 : 0;
    int col = k & (E - 1);
    int j = bp[2 * m + side];
    float p = joint[(size_t)j * E + col];
    d_pair_dup[idx] = dup_pack(p);
}

// ============================================================
// Kernel 3/5: split-K GEMM. out[m][n] = sum_k dup[k][m] * W[k][n]
// grid = (E/512, K/TILE_K), block = 256. Each thread owns 2 cols,
// 16 packed f32x2 accumulators (one per bone).
// ============================================================
__global__ void __launch_bounds__(256) gemm_splitk(
    const float* __restrict__ W,
    const unsigned long long* __restrict__ dup,
    float* __restrict__ partial)
{
    __shared__ unsigned long long sp[TILE_K * M16];  // 32 KB

    int tid = threadIdx.x;
    int k0 = blockIdx.y * TILE_K;

    // cooperative fill of duplicated pair slab (coalesced LDG.64/STS.64)
    const unsigned long long* src = dup + (size_t)k0 * M16;
    #pragma unroll
    for (int i = 0; i < (TILE_K * M16) / 256; i++)
        sp[tid + i * 256] = src[tid + i * 256];
    __syncthreads();

    int n = blockIdx.x * 512 + tid * 2;
    const float* wp = W + (size_t)k0 * E + n;

    unsigned long long acc[M16];
    #pragma unroll
    for (int m = 0; m < M16; m++) acc[m] = 0ULL;  // {0.f, 0.f}

    #pragma unroll 2
    for (int kl = 0; kl < TILE_K; kl++) {
        unsigned long long w = *reinterpret_cast<const unsigned long long*>(wp);
        wp += E;
        const ulonglong2* row = reinterpret_cast<const ulonglong2*>(sp + kl * M16);
        #pragma unroll
        for (int q = 0; q < 8; q++) {
            ulonglong2 r = row[q];             // LDS.128 broadcast
            fma2(acc[2 * q],     w, r.x);
            fma2(acc[2 * q + 1], w, r.y);
        }
    }

    // write partials: [ks][m][E], STG.64 coalesced
    size_t base = ((size_t)blockIdx.y * M16) * E + n;
    #pragma unroll
    for (int m = 0; m < M16; m++) {
        *reinterpret_cast<float2*>(&partial[base + (size_t)m * E]) =
            *reinterpret_cast<float2*>(&acc[m]);
    }
}

// ============================================================
// Kernel 4/6: reduce split-K partials + bias, LayerNorm (+ReLU),
// write either duplicated-transposed h (for GEMM2) or final out.
// grid = 16 (one block per bone row), block = 256.
// ============================================================
template<bool RELU, bool DUP>
__global__ void __launch_bounds__(256) reduce_ln_kernel(
    const float* __restrict__ partial, int ksplits,
    const float* __restrict__ bias,
    const float* __restrict__ gamma,
    const float* __restrict__ beta,
    float* __restrict__ out_lin,
    unsigned long long* __restrict__ out_dup)
{
    int m = blockIdx.x;
    int tid = threadIdx.x;
    __shared__ float vals[E];   // 16 KB
    __shared__ float red[256];
    __shared__ float s_mu, s_rstd;

    float lsum = 0.f;
    #pragma unroll
    for (int i = 0; i < E / 256; i++) {
        int n = tid + i * 256;
        float v = bias[n];
        float a0 = 0.f, a1 = 0.f, a2 = 0.f, a3 = 0.f;
        int ks = 0;
        for (; ks + 4 <= ksplits; ks += 4) {
            a0 += partial[((size_t)(ks + 0) * M16 + m) * E + n];
            a1 += partial[((size_t)(ks + 1) * M16 + m) * E + n];
            a2 += partial[((size_t)(ks + 2) * M16 + m) * E + n];
            a3 += partial[((size_t)(ks + 3) * M16 + m) * E + n];
        }
        for (; ks < ksplits; ks++)
            a0 += partial[((size_t)ks * M16 + m) * E + n];
        v += (a0 + a1) + (a2 + a3);
        vals[n] = v;
        lsum += v;
    }
    red[tid] = lsum;
    __syncthreads();
    for (int off = 128; off > 0; off >>= 1) {
        if (tid < off) red[tid] += red[tid + off];
        __syncthreads();
    }
    if (tid == 0) s_mu = red[0] * (1.0f / E);
    __syncthreads();
    float mu = s_mu;

    float lss = 0.f;
    #pragma unroll
    for (int i = 0; i < E / 256; i++) {
        int n = tid + i * 256;
        float d = vals[n] - mu;
        lss += d * d;
    }
    __syncthreads();
    red[tid] = lss;
    __syncthreads();
    for (int off = 128; off > 0; off >>= 1) {
        if (tid < off) red[tid] += red[tid + off];
        __syncthreads();
    }
    if (tid == 0) s_rstd = rsqrtf(red[0] * (1.0f / E) + LN_EPS);
    __syncthreads();
    float rstd = s_rstd;

    #pragma unroll
    for (int i = 0; i < E / 256; i++) {
        int n = tid + i * 256;
        float y = (vals[n] - mu) * rstd * gamma[n] + beta[n];
        if (RELU) y = fmaxf(y, 0.f);
        if (DUP)
            out_dup[(size_t)n * M16 + m] = dup_pack(y);
        else
            out_lin[(size_t)m * E + n] = y;
    }
}

// ============================================================
// launcher
// ============================================================
extern "C" void kernel_launch(void* const* d_in, const int* in_sizes, int n_in,
                              void* d_out, int out_size)
{
    const float* emb = (const float*)d_in[0];
    const float* W1  = (const float*)d_in[1];
    const float* b1  = (const float*)d_in[2];
    const float* g1  = (const float*)d_in[3];
    const float* be1 = (const float*)d_in[4];
    const float* W2  = (const float*)d_in[5];
    const float* b2  = (const float*)d_in[6];
    const float* g2  = (const float*)d_in[7];
    const float* be2 = (const float*)d_in[8];
    const int*   bp  = (const int*)d_in[9];

    float* out = (float*)d_out;
    float* out_joint = out;                      // [17][4096]
    float* out_bone  = out + (size_t)J * E;      // [16][4096]

    unsigned long long* pair_dup_p; cudaGetSymbolAddress((void**)&pair_dup_p, d_pair_dup);
    unsigned long long* h_dup_p;    cudaGetSymbolAddress((void**)&h_dup_p, d_h_dup);
    float* partial_p;               cudaGetSymbolAddress((void**)&partial_p, d_partial);

    // 1. L2-normalize joints -> output (and serves as gather source)
    normalize_kernel<<<J, 256>>>(emb, out_joint);

    // 2. build duplicated pair activations [K1][16]
    pair_dup_kernel<<<(K1 * M16) / 256, 256>>>(out_joint, bp);

    // 3. GEMM1 split-K: pair @ W1 -> partials
    gemm_splitk<<<dim3(NTILES, KS1), 256>>>(W1, pair_dup_p, partial_p);

    // 4. reduce + bias + LN + ReLU -> h duplicated-transposed
    reduce_ln_kernel<true, true><<<M16, 256>>>(
        partial_p, KS1, b1, g1, be1, nullptr, h_dup_p);

    // 5. GEMM2 split-K: h @ W2 -> partials (reuse buffer)
    gemm_splitk<<<dim3(NTILES, KS2), 256>>>(W2, h_dup_p, partial_p);

    // 6. reduce + bias + LN -> final bone features
    reduce_ln_kernel<false, false><<<M16, 256>>>(
        partial_p, KS2, b2, g2, be2, out_bone, nullptr);
}

// round 2
// speedup vs baseline: 2.4252x; 2.4252x over previous
#include <cuda_runtime.h>
#include <cstdint>

// Problem constants
#define J   17
#define E   4096
#define M16 16          // number of bones
#define K1  (2*E)       // 8192
#define K2  E           // 4096
#define TILE_K 256
#define KS1 (K1/TILE_K) // 32
#define KS2 (K2/TILE_K) // 16
#define NTILES (E/512)  // 8 (256 threads * 2 cols)
#define CH (E/256)      // 16 column chunks for reduce kernels
#define LN_EPS 1e-5f
#define PFB 16          // prefetch batch in GEMM mainloop

// -------- device scratch (no allocations allowed) --------
__device__ unsigned long long d_pair_dup[K1 * M16];   // 1 MB: {p,p} per (k,m)
__device__ unsigned long long d_h_dup  [K2 * M16];    // 512 KB
__device__ float  d_partial[KS1 * M16 * E];           // 8 MB, reused by GEMM2
__device__ float  d_sums[M16 * E];                    // 256 KB reduced pre-LN values
__device__ float2 d_stats[M16 * CH];                  // per-(row,chunk) sum/sumsq
__device__ float2 d_mu_rstd[M16];                     // per-row LN stats

// -------- helpers --------
__device__ __forceinline__ void fma2(unsigned long long& d,
                                     unsigned long long a,
                                     unsigned long long b) {
    asm("fma.rn.f32x2 %0, %1, %2, %0;" : "+l"(d) : "l"(a), "l"(b));
}

__device__ __forceinline__ unsigned long long dup_pack(float p) {
    unsigned int u = __float_as_uint(p);
    return ((unsigned long long)u << 32) | (unsigned long long)u;
}

// ============================================================
// Kernel 1: L2-normalize joint embeddings, scale by sqrt(E)=64.
// grid=17, block=256. Writes joint part of output.
// ============================================================
__global__ void __launch_bounds__(256) normalize_kernel(
    const float* __restrict__ x, float* __restrict__ out_joint)
{
    int row = blockIdx.x;
    int tid = threadIdx.x;
    const float* xr = x + (size_t)row * E;

    float s = 0.f;
    float v[E / 256];
    #pragma unroll
    for (int i = 0; i < E / 256; i++) {
        v[i] = xr[tid + i * 256];
        s += v[i] * v[i];
    }
    __shared__ float red[256];
    red[tid] = s;
    __syncthreads();
    for (int off = 128; off > 0; off >>= 1) {
        if (tid < off) red[tid] += red[tid + off];
        __syncthreads();
    }
    __shared__ float s_inv;
    if (tid == 0) {
        float nrm = sqrtf(red[0]);
        s_inv = 64.0f / fmaxf(nrm, 1e-12f);
    }
    __syncthreads();
    float inv = s_inv;
    #pragma unroll
    for (int i = 0; i < E / 256; i++)
        out_joint[(size_t)row * E + tid + i * 256] = v[i] * inv;
}

// ============================================================
// Kernel 2: build duplicated pair activations, [K1][16] of {p,p}
// ============================================================
__global__ void __launch_bounds__(256) pair_dup_kernel(
    const float* __restrict__ joint, const int* __restrict__ bp)
{
    int idx = blockIdx.x * 256 + threadIdx.x;   // idx = k*16 + m
    int k = idx >> 4;
    int m = idx & 15;
    int side = (k >= E) ? 1 : 0;
    int col = k & (E - 1);
    int j = bp[2 * m + side];
    float p = joint[(size_t)j * E + col];
    d_pair_dup[idx] = dup_pack(p);
}

// ============================================================
// Kernel 3/7: split-K GEMM. out[m][n] = sum_k dup[k][m] * W[k][n]
// grid = (E/512, K/TILE_K), block = 256. Each thread owns 2 cols,
// 16 packed f32x2 accumulators. Deep LDG prefetch (PFB rows) for MLP.
// ============================================================
__global__ void __launch_bounds__(256) gemm_splitk(
    const float* __restrict__ W,
    const unsigned long long* __restrict__ dup,
    float* __restrict__ partial)
{
    __shared__ unsigned long long sp[TILE_K * M16];  // 32 KB

    int tid = threadIdx.x;
    int k0 = blockIdx.y * TILE_K;

    const unsigned long long* src = dup + (size_t)k0 * M16;
    #pragma unroll
    for (int i = 0; i < (TILE_K * M16) / 256; i++)
        sp[tid + i * 256] = src[tid + i * 256];
    __syncthreads();

    int n = blockIdx.x * 512 + tid * 2;
    const float* wp = W + (size_t)k0 * E + n;

    unsigned long long acc[M16];
    #pragma unroll
    for (int m = 0; m < M16; m++) acc[m] = 0ULL;

    for (int kb = 0; kb < TILE_K; kb += PFB) {
        // front-batched loads: PFB outstanding LDG.64 per thread
        unsigned long long wv[PFB];
        #pragma unroll
        for (int j = 0; j < PFB; j++)
            wv[j] = *reinterpret_cast<const unsigned long long*>(
                        wp + (size_t)(kb + j) * E);
        #pragma unroll
        for (int j = 0; j < PFB; j++) {
            const ulonglong2* row =
                reinterpret_cast<const ulonglong2*>(sp + (kb + j) * M16);
            #pragma unroll
            for (int q = 0; q < 8; q++) {
                ulonglong2 r = row[q];             // LDS.128 broadcast
                fma2(acc[2 * q],     wv[j], r.x);
                fma2(acc[2 * q + 1], wv[j], r.y);
            }
        }
    }

    size_t base = ((size_t)blockIdx.y * M16) * E + n;
    #pragma unroll
    for (int m = 0; m < M16; m++)
        *reinterpret_cast<float2*>(&partial[base + (size_t)m * E]) =
            *reinterpret_cast<float2*>(&acc[m]);
}

// ============================================================
// Kernel 4/8: column-parallel split-K reduce + bias.
// grid = (CH, M16) = 256 blocks. Writes sums and per-chunk stats.
// ============================================================
__global__ void __launch_bounds__(256) splitk_reduce_kernel(
    const float* __restrict__ partial, int ksplits,
    const float* __restrict__ bias,
    float* __restrict__ sums, float2* __restrict__ stats)
{
    int m   = blockIdx.y;
    int tid = threadIdx.x;
    int n   = blockIdx.x * 256 + tid;

    float a0 = bias[n], a1 = 0.f, a2 = 0.f, a3 = 0.f;
    const float* p = partial + (size_t)m * E + n;
    int ks = 0;
    for (; ks + 4 <= ksplits; ks += 4) {
        a0 += p[(size_t)(ks + 0) * M16 * E];
        a1 += p[(size_t)(ks + 1) * M16 * E];
        a2 += p[(size_t)(ks + 2) * M16 * E];
        a3 += p[(size_t)(ks + 3) * M16 * E];
    }
    for (; ks < ksplits; ks++)
        a0 += p[(size_t)ks * M16 * E];
    float v = (a0 + a1) + (a2 + a3);
    sums[(size_t)m * E + n] = v;

    __shared__ float rs[256], rq[256];
    rs[tid] = v;
    rq[tid] = v * v;
    __syncthreads();
    for (int off = 128; off > 0; off >>= 1) {
        if (tid < off) { rs[tid] += rs[tid + off]; rq[tid] += rq[tid + off]; }
        __syncthreads();
    }
    if (tid == 0)
        stats[m * CH + blockIdx.x] = make_float2(rs[0], rq[0]);
}

// ============================================================
// Kernel 5/9: finalize LN stats. 1 block, 256 threads (= M16*CH).
// ============================================================
__global__ void __launch_bounds__(256) stats_kernel(
    const float2* __restrict__ stats, float2* __restrict__ mu_rstd)
{
    int t = threadIdx.x;           // t = m*CH + c, CH == 16
    float2 s = stats[t];
    #pragma unroll
    for (int off = 8; off > 0; off >>= 1) {
        s.x += __shfl_down_sync(0xffffffffu, s.x, off);
        s.y += __shfl_down_sync(0xffffffffu, s.y, off);
    }
    if ((t & 15) == 0) {
        int m = t >> 4;
        float mu  = s.x * (1.0f / E);
        float var = s.y * (1.0f / E) - mu * mu;
        mu_rstd[m] = make_float2(mu, rsqrtf(var + LN_EPS));
    }
}

// ============================================================
// Kernel 6/10: apply LN (+ReLU), write dup-transposed h or final out.
// grid = (CH, M16) = 256 blocks.
// ============================================================
template<bool RELU, bool DUP>
__global__ void __launch_bounds__(256) apply_ln_kernel(
    const float* __restrict__ sums,
    const float2* __restrict__ mu_rstd,
    const float* __restrict__ gamma,
    const float* __restrict__ beta,
    float* __restrict__ out_lin,
    unsigned long long* __restrict__ out_dup)
{
    int m = blockIdx.y;
    int n = blockIdx.x * 256 + threadIdx.x;
    float2 mr = mu_rstd[m];
    float y = (sums[(size_t)m * E + n] - mr.x) * mr.y * gamma[n] + beta[n];
    if (RELU) y = fmaxf(y, 0.f);
    if (DUP)
        out_dup[(size_t)n * M16 + m] = dup_pack(y);
    else
        out_lin[(size_t)m * E + n] = y;
}

// ============================================================
// launcher
// ============================================================
extern "C" void kernel_launch(void* const* d_in, const int* in_sizes, int n_in,
                              void* d_out, int out_size)
{
    const float* emb = (const float*)d_in[0];
    const float* W1  = (const float*)d_in[1];
    const float* b1  = (const float*)d_in[2];
    const float* g1  = (const float*)d_in[3];
    const float* be1 = (const float*)d_in[4];
    const float* W2  = (const float*)d_in[5];
    const float* b2  = (const float*)d_in[6];
    const float* g2  = (const float*)d_in[7];
    const float* be2 = (const float*)d_in[8];
    const int*   bp  = (const int*)d_in[9];

    float* out = (float*)d_out;
    float* out_joint = out;                      // [17][4096]
    float* out_bone  = out + (size_t)J * E;      // [16][4096]

    unsigned long long* pair_dup_p; cudaGetSymbolAddress((void**)&pair_dup_p, d_pair_dup);
    unsigned long long* h_dup_p;    cudaGetSymbolAddress((void**)&h_dup_p, d_h_dup);
    float*  partial_p;              cudaGetSymbolAddress((void**)&partial_p, d_partial);
    float*  sums_p;                 cudaGetSymbolAddress((void**)&sums_p, d_sums);
    float2* stats_p;                cudaGetSymbolAddress((void**)&stats_p, d_stats);
    float2* mu_p;                   cudaGetSymbolAddress((void**)&mu_p, d_mu_rstd);

    // 1. L2-normalize joints -> output (also serves as gather source)
    normalize_kernel<<<J, 256>>>(emb, out_joint);

    // 2. build duplicated pair activations [K1][16]
    pair_dup_kernel<<<(K1 * M16) / 256, 256>>>(out_joint, bp);

    // 3. GEMM1 split-K: pair @ W1 -> partials
    gemm_splitk<<<dim3(NTILES, KS1), 256>>>(W1, pair_dup_p, partial_p);

    // 4-6. reduce + bias; LN stats; apply LN+ReLU -> h dup-transposed
    splitk_reduce_kernel<<<dim3(CH, M16), 256>>>(partial_p, KS1, b1, sums_p, stats_p);
    stats_kernel<<<1, 256>>>(stats_p, mu_p);
    apply_ln_kernel<true, true><<<dim3(CH, M16), 256>>>(
        sums_p, mu_p, g1, be1, nullptr, h_dup_p);

    // 7. GEMM2 split-K: h @ W2 -> partials (reuse buffer)
    gemm_splitk<<<dim3(NTILES, KS2), 256>>>(W2, h_dup_p, partial_p);

    // 8-10. reduce + bias; LN stats; apply LN -> final bone features
    splitk_reduce_kernel<<<dim3(CH, M16), 256>>>(partial_p, KS2, b2, sums_p, stats_p);
    stats_kernel<<<1, 256>>>(stats_p, mu_p);
    apply_ln_kernel<false, false><<<dim3(CH, M16), 256>>>(
        sums_p, mu_p, g2, be2, out_bone, nullptr);
}

// round 3
// speedup vs baseline: 2.5985x; 1.0715x over previous
#include <cuda_runtime.h>
#include <cstdint>

// Problem constants
#define J   17
#define E   4096
#define M16 16          // number of bones
#define K1  (2*E)       // 8192
#define K2  E           // 4096
#define TK1 256         // GEMM1 K-slab
#define TK2 128         // GEMM2 K-slab
#define KS  32          // both GEMMs produce 32 K-slabs
#define NTILES (E/512)  // 8 (256 threads * 2 cols)
#define CH (E/512)      // 8 column chunks (float2) for reduce kernels
#define LN_EPS 1e-5f
#define PFB 8           // prefetch batch (double buffered)

typedef unsigned long long ull;

// -------- device scratch (no allocations allowed) --------
__device__ ull    d_pair_dup[K1 * M16];   // 1 MB: {p,p} per (k,m)
__device__ ull    d_h_dup  [K2 * M16];    // 512 KB
__device__ float  d_partial[KS * M16 * E];            // 8 MB, reused by GEMM2
__device__ float  d_sums[M16 * E];                    // 256 KB pre-LN values
__device__ float2 d_stats[M16 * CH];                  // per-(row,chunk) sum/sumsq
__device__ float2 d_mu_rstd[M16];                     // per-row LN stats

// -------- helpers --------
__device__ __forceinline__ void fma2(ull& d, ull a, ull b) {
    asm("fma.rn.f32x2 %0, %1, %2, %0;" : "+l"(d) : "l"(a), "l"(b));
}

__device__ __forceinline__ ull dup_pack(float p) {
    unsigned int u = __float_as_uint(p);
    return ((ull)u << 32) | (ull)u;
}

// ============================================================
// Kernel 1: L2-normalize joint embeddings, scale by sqrt(E)=64.
// ============================================================
__global__ void __launch_bounds__(256) normalize_kernel(
    const float* __restrict__ x, float* __restrict__ out_joint)
{
    int row = blockIdx.x;
    int tid = threadIdx.x;
    const float* xr = x + (size_t)row * E;

    float s = 0.f;
    float v[E / 256];
    #pragma unroll
    for (int i = 0; i < E / 256; i++) {
        v[i] = xr[tid + i * 256];
        s += v[i] * v[i];
    }
    __shared__ float red[256];
    red[tid] = s;
    __syncthreads();
    for (int off = 128; off > 0; off >>= 1) {
        if (tid < off) red[tid] += red[tid + off];
        __syncthreads();
    }
    __shared__ float s_inv;
    if (tid == 0) {
        float nrm = sqrtf(red[0]);
        s_inv = 64.0f / fmaxf(nrm, 1e-12f);
    }
    __syncthreads();
    float inv = s_inv;
    #pragma unroll
    for (int i = 0; i < E / 256; i++)
        out_joint[(size_t)row * E + tid + i * 256] = v[i] * inv;
}

// ============================================================
// Kernel 2: build duplicated pair activations, [K1][16] of {p,p}
// ============================================================
__global__ void __launch_bounds__(256) pair_dup_kernel(
    const float* __restrict__ joint, const int* __restrict__ bp)
{
    int idx = blockIdx.x * 256 + threadIdx.x;   // idx = k*16 + m
    int k = idx >> 4;
    int m = idx & 15;
    int side = (k >= E) ? 1 : 0;
    int col = k & (E - 1);
    int j = bp[2 * m + side];
    float p = joint[(size_t)j * E + col];
    d_pair_dup[idx] = dup_pack(p);
}

// ============================================================
// GEMM (split-K, software-pipelined). out[m][n]=sum_k dup[k][m]*W[k][n]
// grid=(E/512, K/TK), block=256. 2 cols/thread, 16 f32x2 accumulators.
// Double-buffered register prefetch of W rows for sustained MLP.
// ============================================================
template<int TK>
__global__ void __launch_bounds__(256) gemm_splitk(
    const float* __restrict__ W,
    const ull* __restrict__ dup,
    float* __restrict__ partial)
{
    __shared__ ull sp[TK * M16];

    int tid = threadIdx.x;
    int k0 = blockIdx.y * TK;

    const ull* src = dup + (size_t)k0 * M16;
    #pragma unroll
    for (int i = 0; i < (TK * M16) / 256; i++)
        sp[tid + i * 256] = src[tid + i * 256];
    __syncthreads();

    int n = blockIdx.x * 512 + tid * 2;
    const float* wp = W + (size_t)k0 * E + n;

    ull acc[M16];
    #pragma unroll
    for (int m = 0; m < M16; m++) acc[m] = 0ULL;

    ull wv0[PFB], wv1[PFB];

    #pragma unroll
    for (int j = 0; j < PFB; j++)
        wv0[j] = *reinterpret_cast<const ull*>(wp + (size_t)j * E);

    #pragma unroll 1
    for (int kb = 0; kb < TK - 2 * PFB; kb += 2 * PFB) {
        // prefetch next chunk while consuming wv0
        #pragma unroll
        for (int j = 0; j < PFB; j++)
            wv1[j] = *reinterpret_cast<const ull*>(wp + (size_t)(kb + PFB + j) * E);
        #pragma unroll
        for (int j = 0; j < PFB; j++) {
            const ulonglong2* row =
                reinterpret_cast<const ulonglong2*>(sp + (kb + j) * M16);
            #pragma unroll
            for (int q = 0; q < 8; q++) {
                ulonglong2 r = row[q];             // LDS.128 broadcast
                fma2(acc[2 * q],     wv0[j], r.x);
                fma2(acc[2 * q + 1], wv0[j], r.y);
            }
        }
        #pragma unroll
        for (int j = 0; j < PFB; j++)
            wv0[j] = *reinterpret_cast<const ull*>(wp + (size_t)(kb + 2 * PFB + j) * E);
        #pragma unroll
        for (int j = 0; j < PFB; j++) {
            const ulonglong2* row =
                reinterpret_cast<const ulonglong2*>(sp + (kb + PFB + j) * M16);
            #pragma unroll
            for (int q = 0; q < 8; q++) {
                ulonglong2 r = row[q];
                fma2(acc[2 * q],     wv1[j], r.x);
                fma2(acc[2 * q + 1], wv1[j], r.y);
            }
        }
    }
    // tail: kb = TK-2*PFB
    {
        const int kb = TK - 2 * PFB;
        #pragma unroll
        for (int j = 0; j < PFB; j++)
            wv1[j] = *reinterpret_cast<const ull*>(wp + (size_t)(kb + PFB + j) * E);
        #pragma unroll
        for (int j = 0; j < PFB; j++) {
            const ulonglong2* row =
                reinterpret_cast<const ulonglong2*>(sp + (kb + j) * M16);
            #pragma unroll
            for (int q = 0; q < 8; q++) {
                ulonglong2 r = row[q];
                fma2(acc[2 * q],     wv0[j], r.x);
                fma2(acc[2 * q + 1], wv0[j], r.y);
            }
        }
        #pragma unroll
        for (int j = 0; j < PFB; j++) {
            const ulonglong2* row =
                reinterpret_cast<const ulonglong2*>(sp + (kb + PFB + j) * M16);
            #pragma unroll
            for (int q = 0; q < 8; q++) {
                ulonglong2 r = row[q];
                fma2(acc[2 * q],     wv1[j], r.x);
                fma2(acc[2 * q + 1], wv1[j], r.y);
            }
        }
    }

    size_t base = ((size_t)blockIdx.y * M16) * E + n;
    #pragma unroll
    for (int m = 0; m < M16; m++)
        *reinterpret_cast<float2*>(&partial[base + (size_t)m * E]) =
            *reinterpret_cast<float2*>(&acc[m]);
}

// ============================================================
// Column-parallel split-K reduce + bias (float2).
// grid = (CH, M16) = 128 blocks, block=256.
// ============================================================
__global__ void __launch_bounds__(256) splitk_reduce_kernel(
    const float2* __restrict__ partial2,
    const float2* __restrict__ bias2,
    float2* __restrict__ sums2, float2* __restrict__ stats)
{
    int m   = blockIdx.y;
    int tid = threadIdx.x;
    int n2  = blockIdx.x * 256 + tid;           // float2 column index

    const float2* p = partial2 + (size_t)m * (E / 2) + n2;
    const size_t stride = (size_t)M16 * (E / 2);

    float2 b = bias2[n2];
    float a0x = b.x, a0y = b.y, a1x = 0.f, a1y = 0.f;
    float a2x = 0.f, a2y = 0.f, a3x = 0.f, a3y = 0.f;
    #pragma unroll
    for (int ks = 0; ks < KS; ks += 4) {
        float2 v0 = p[(size_t)(ks + 0) * stride];
        float2 v1 = p[(size_t)(ks + 1) * stride];
        float2 v2 = p[(size_t)(ks + 2) * stride];
        float2 v3 = p[(size_t)(ks + 3) * stride];
        a0x += v0.x; a0y += v0.y;
        a1x += v1.x; a1y += v1.y;
        a2x += v2.x; a2y += v2.y;
        a3x += v3.x; a3y += v3.y;
    }
    float vx = (a0x + a1x) + (a2x + a3x);
    float vy = (a0y + a1y) + (a2y + a3y);
    sums2[(size_t)m * (E / 2) + n2] = make_float2(vx, vy);

    __shared__ float rs[256], rq[256];
    rs[tid] = vx + vy;
    rq[tid] = vx * vx + vy * vy;
    __syncthreads();
    for (int off = 128; off > 0; off >>= 1) {
        if (tid < off) { rs[tid] += rs[tid + off]; rq[tid] += rq[tid + off]; }
        __syncthreads();
    }
    if (tid == 0)
        stats[m * CH + blockIdx.x] = make_float2(rs[0], rq[0]);
}

// ============================================================
// Finalize LN stats. 1 block, 128 threads (= M16*CH).
// ============================================================
__global__ void __launch_bounds__(128) stats_kernel(
    const float2* __restrict__ stats, float2* __restrict__ mu_rstd)
{
    int t = threadIdx.x;           // t = m*CH + c, CH == 8
    float2 s = stats[t];
    #pragma unroll
    for (int off = 4; off > 0; off >>= 1) {
        s.x += __shfl_down_sync(0xffffffffu, s.x, off, 8);
        s.y += __shfl_down_sync(0xffffffffu, s.y, off, 8);
    }
    if ((t & 7) == 0) {
        int m = t >> 3;
        float mu  = s.x * (1.0f / E);
        float var = s.y * (1.0f / E) - mu * mu;
        mu_rstd[m] = make_float2(mu, rsqrtf(var + LN_EPS));
    }
}

// ============================================================
// Apply LN (+ReLU), write dup-transposed h or final out (float2).
// grid = (CH, M16) = 128 blocks.
// ============================================================
template<bool RELU, bool DUP>
__global__ void __launch_bounds__(256) apply_ln_kernel(
    const float2* __restrict__ sums2,
    const float2* __restrict__ mu_rstd,
    const float2* __restrict__ gamma2,
    const float2* __restrict__ beta2,
    float2* __restrict__ out_lin2,
    ull* __restrict__ out_dup)
{
    int m  = blockIdx.y;
    int n2 = blockIdx.x * 256 + threadIdx.x;
    float2 mr = mu_rstd[m];
    float2 v  = sums2[(size_t)m * (E / 2) + n2];
    float2 g  = gamma2[n2];
    float2 bb = beta2[n2];
    float yx = (v.x - mr.x) * mr.y * g.x + bb.x;
    float yy = (v.y - mr.x) * mr.y * g.y + bb.y;
    if (RELU) { yx = fmaxf(yx, 0.f); yy = fmaxf(yy, 0.f); }
    if (DUP) {
        int n = 2 * n2;
        out_dup[(size_t)n * M16 + m]       = dup_pack(yx);
        out_dup[(size_t)(n + 1) * M16 + m] = dup_pack(yy);
    } else {
        out_lin2[(size_t)m * (E / 2) + n2] = make_float2(yx, yy);
    }
}

// ============================================================
// launcher
// ============================================================
extern "C" void kernel_launch(void* const* d_in, const int* in_sizes, int n_in,
                              void* d_out, int out_size)
{
    const float* emb = (const float*)d_in[0];
    const float* W1  = (const float*)d_in[1];
    const float* b1  = (const float*)d_in[2];
    const float* g1  = (const float*)d_in[3];
    const float* be1 = (const float*)d_in[4];
    const float* W2  = (const float*)d_in[5];
    const float* b2  = (const float*)d_in[6];
    const float* g2  = (const float*)d_in[7];
    const float* be2 = (const float*)d_in[8];
    const int*   bp  = (const int*)d_in[9];

    float* out = (float*)d_out;
    float* out_joint = out;                      // [17][4096]
    float* out_bone  = out + (size_t)J * E;      // [16][4096]

    ull*    pair_dup_p; cudaGetSymbolAddress((void**)&pair_dup_p, d_pair_dup);
    ull*    h_dup_p;    cudaGetSymbolAddress((void**)&h_dup_p, d_h_dup);
    float*  partial_p;  cudaGetSymbolAddress((void**)&partial_p, d_partial);
    float*  sums_p;     cudaGetSymbolAddress((void**)&sums_p, d_sums);
    float2* stats_p;    cudaGetSymbolAddress((void**)&stats_p, d_stats);
    float2* mu_p;       cudaGetSymbolAddress((void**)&mu_p, d_mu_rstd);

    // 1. L2-normalize joints -> output (also serves as gather source)
    normalize_kernel<<<J, 256>>>(emb, out_joint);

    // 2. build duplicated pair activations [K1][16]
    pair_dup_kernel<<<(K1 * M16) / 256, 256>>>(out_joint, bp);

    // 3. GEMM1 split-K (TK=256): pair @ W1 -> partials
    gemm_splitk<TK1><<<dim3(NTILES, K1 / TK1), 256>>>(W1, pair_dup_p, partial_p);

    // 4-6. reduce + bias; LN stats; apply LN+ReLU -> h dup-transposed
    splitk_reduce_kernel<<<dim3(CH, M16), 256>>>(
        (const float2*)partial_p, (const float2*)b1, (float2*)sums_p, stats_p);
    stats_kernel<<<1, 128>>>(stats_p, mu_p);
    apply_ln_kernel<true, true><<<dim3(CH, M16), 256>>>(
        (const float2*)sums_p, mu_p, (const float2*)g1, (const float2*)be1,
        nullptr, h_dup_p);

    // 7. GEMM2 split-K (TK=128): h @ W2 -> partials (reuse buffer)
    gemm_splitk<TK2><<<dim3(NTILES, K2 / TK2), 256>>>(W2, h_dup_p, partial_p);

    // 8-10. reduce + bias; LN stats; apply LN -> final bone features
    splitk_reduce_kernel<<<dim3(CH, M16), 256>>>(
        (const float2*)partial_p, (const float2*)b2, (float2*)sums_p, stats_p);
    stats_kernel<<<1, 128>>>(stats_p, mu_p);
    apply_ln_kernel<false, false><<<dim3(CH, M16), 256>>>(
        (const float2*)sums_p, mu_p, (const float2*)g2, (const float2*)be2,
        (float2*)out_bone, nullptr);
}

// round 4
// speedup vs baseline: 2.8282x; 1.0884x over previous
#include <cuda_runtime.h>
#include <cstdint>

#define J   17
#define E   4096
#define M16 16
#define K1  (2*E)       // 8192
#define K2  E           // 4096
#define TK1 256         // GEMM1 K-slab -> 32 slabs
#define TK2 128         // GEMM2 K-slab -> 32 slabs
#define KS  32
#define LN_EPS 1e-5f

typedef unsigned long long ull;

// -------- device scratch --------
__device__ ull    d_h_dup[K2 * M16];        // 512 KB {h,h} pairs, [k][m]
__device__ float  d_partial[KS * M16 * E];  // 8 MB
__device__ float  d_sums[M16 * E];          // 256 KB
__device__ float2 d_stats[M16 * 4];         // per-(row,chunk) sum/sumsq

__device__ __forceinline__ void fma2(ull& d, ull a, ull b) {
    asm("fma.rn.f32x2 %0, %1, %2, %0;" : "+l"(d) : "l"(a), "l"(b));
}
__device__ __forceinline__ ull dup_pack(float p) {
    unsigned int u = __float_as_uint(p);
    return ((ull)u << 32) | (ull)u;
}

// ============================================================
// L2-normalize joints, scale by sqrt(E)=64. grid=17, block=256.
// ============================================================
__global__ void __launch_bounds__(256) normalize_kernel(
    const float* __restrict__ x, float* __restrict__ out_joint)
{
    int row = blockIdx.x;
    int tid = threadIdx.x;
    const float* xr = x + (size_t)row * E;

    float s = 0.f;
    float v[E / 256];
    #pragma unroll
    for (int i = 0; i < E / 256; i++) {
        v[i] = xr[tid + i * 256];
        s += v[i] * v[i];
    }
    __shared__ float red[256];
    red[tid] = s;
    __syncthreads();
    for (int off = 128; off > 0; off >>= 1) {
        if (tid < off) red[tid] += red[tid + off];
        __syncthreads();
    }
    __shared__ float s_inv;
    if (tid == 0) s_inv = 64.0f / fmaxf(sqrtf(red[0]), 1e-12f);
    __syncthreads();
    float inv = s_inv;
    #pragma unroll
    for (int i = 0; i < E / 256; i++)
        out_joint[(size_t)row * E + tid + i * 256] = v[i] * inv;
}

// ============================================================
// Split-K GEMM, 4 cols/thread. out[m][n] = sum_k act[k][m]*W[k][n]
// grid=(E/1024, K/TK)=(4,32), block=256.
// GATHER: build activation slab from joint+bone_pairs (GEMM1);
// else copy pre-duplicated h slab (GEMM2).
// ============================================================
template<int TK, bool GATHER>
__global__ void __launch_bounds__(256) gemm_splitk(
    const float* __restrict__ W,
    const float* __restrict__ joint,
    const int*   __restrict__ bp,
    const ull*   __restrict__ dupsrc,
    float* __restrict__ partial)
{
    __shared__ ull sp[TK * M16];

    int tid = threadIdx.x;
    int k0 = blockIdx.y * TK;

    if (GATHER) {
        int m = tid & 15;
        int j0 = bp[2 * m];
        int j1 = bp[2 * m + 1];
        const float* r0 = joint + (size_t)j0 * E;
        const float* r1 = joint + (size_t)j1 * E;
        #pragma unroll
        for (int i = 0; i < (TK * M16) / 256; i++) {
            int kl = (tid >> 4) + i * 16;
            int k = k0 + kl;
            int col = k & (E - 1);
            float p = (k < E) ? r0[col] : r1[col];
            sp[kl * M16 + m] = dup_pack(p);
        }
    } else {
        const ull* src = dupsrc + (size_t)k0 * M16;
        #pragma unroll
        for (int i = 0; i < (TK * M16) / 256; i++)
            sp[tid + i * 256] = src[tid + i * 256];
    }
    __syncthreads();

    int n = blockIdx.x * 1024 + tid * 4;
    const float* wp = W + (size_t)k0 * E + n;

    ull acc[M16][2];
    #pragma unroll
    for (int m = 0; m < M16; m++) { acc[m][0] = 0ULL; acc[m][1] = 0ULL; }

    ulonglong2 wv0[4], wv1[4];

    #pragma unroll
    for (int j = 0; j < 4; j++)
        wv0[j] = *reinterpret_cast<const ulonglong2*>(wp + (size_t)j * E);

    #define CONSUME(WV, KB)                                                   \
        _Pragma("unroll")                                                     \
        for (int j = 0; j < 4; j++) {                                         \
            const ulonglong2* row =                                           \
                reinterpret_cast<const ulonglong2*>(sp + ((KB) + j) * M16);   \
            _Pragma("unroll")                                                 \
            for (int q = 0; q < 8; q++) {                                     \
                ulonglong2 r = row[q];                                        \
                fma2(acc[2*q  ][0], WV[j].x, r.x);                            \
                fma2(acc[2*q  ][1], WV[j].y, r.x);                            \
                fma2(acc[2*q+1][0], WV[j].x, r.y);                            \
                fma2(acc[2*q+1][1], WV[j].y, r.y);                            \
            }                                                                 \
        }

    #pragma unroll 1
    for (int cb = 0; cb < TK - 8; cb += 8) {
        #pragma unroll
        for (int j = 0; j < 4; j++)
            wv1[j] = *reinterpret_cast<const ulonglong2*>(wp + (size_t)(cb + 4 + j) * E);
        CONSUME(wv0, cb)
        #pragma unroll
        for (int j = 0; j < 4; j++)
            wv0[j] = *reinterpret_cast<const ulonglong2*>(wp + (size_t)(cb + 8 + j) * E);
        CONSUME(wv1, cb + 4)
    }
    {
        const int cb = TK - 8;
        #pragma unroll
        for (int j = 0; j < 4; j++)
            wv1[j] = *reinterpret_cast<const ulonglong2*>(wp + (size_t)(cb + 4 + j) * E);
        CONSUME(wv0, cb)
        CONSUME(wv1, cb + 4)
    }
    #undef CONSUME

    size_t base = ((size_t)blockIdx.y * M16) * E + n;
    #pragma unroll
    for (int m = 0; m < M16; m++) {
        ulonglong2 o; o.x = acc[m][0]; o.y = acc[m][1];
        *reinterpret_cast<ulonglong2*>(&partial[base + (size_t)m * E]) = o;
    }
}

// ============================================================
// Split-K reduce + bias (float4), per-chunk LN stats.
// grid = (4, 16), block=256. thread -> one float4 column.
// ============================================================
__global__ void __launch_bounds__(256) splitk_reduce_kernel(
    const float4* __restrict__ partial4,
    const float4* __restrict__ bias4,
    float4* __restrict__ sums4, float2* __restrict__ stats)
{
    int m   = blockIdx.y;
    int tid = threadIdx.x;
    int n4  = blockIdx.x * 256 + tid;              // 0..1023

    const float4* p = partial4 + (size_t)m * (E / 4) + n4;
    const size_t stride = (size_t)M16 * (E / 4);

    float4 a[8];
    a[0] = bias4[n4];
    #pragma unroll
    for (int r = 1; r < 8; r++) a[r] = make_float4(0.f, 0.f, 0.f, 0.f);

    #pragma unroll
    for (int ks = 0; ks < KS; ks += 8) {
        #pragma unroll
        for (int r = 0; r < 8; r++) {
            float4 v = p[(size_t)(ks + r) * stride];
            a[r].x += v.x; a[r].y += v.y; a[r].z += v.z; a[r].w += v.w;
        }
    }
    #pragma unroll
    for (int r = 4; r > 0; r >>= 1)
        #pragma unroll
        for (int s = 0; s < r; s++) {
            a[s].x += a[s + r].x; a[s].y += a[s + r].y;
            a[s].z += a[s + r].z; a[s].w += a[s + r].w;
        }
    float4 v = a[0];
    sums4[(size_t)m * (E / 4) + n4] = v;

    __shared__ float rs[256], rq[256];
    rs[tid] = (v.x + v.y) + (v.z + v.w);
    rq[tid] = (v.x * v.x + v.y * v.y) + (v.z * v.z + v.w * v.w);
    __syncthreads();
    for (int off = 128; off > 0; off >>= 1) {
        if (tid < off) { rs[tid] += rs[tid + off]; rq[tid] += rq[tid + off]; }
        __syncthreads();
    }
    if (tid == 0)
        stats[m * 4 + blockIdx.x] = make_float2(rs[0], rq[0]);
}

// ============================================================
// Apply LN (+ReLU). Stats finalized redundantly per block (32B read).
// grid = (4, 16), block=256.
// ============================================================
template<bool RELU, bool DUP>
__global__ void __launch_bounds__(256) apply_ln_kernel(
    const float4* __restrict__ sums4,
    const float2* __restrict__ stats,
    const float4* __restrict__ gamma4,
    const float4* __restrict__ beta4,
    float4* __restrict__ out4,
    ull* __restrict__ out_dup)
{
    int m  = blockIdx.y;
    int n4 = blockIdx.x * 256 + threadIdx.x;

    float2 s0 = stats[m * 4 + 0];
    float2 s1 = stats[m * 4 + 1];
    float2 s2 = stats[m * 4 + 2];
    float2 s3 = stats[m * 4 + 3];
    float sum = (s0.x + s1.x) + (s2.x + s3.x);
    float sq  = (s0.y + s1.y) + (s2.y + s3.y);
    float mu   = sum * (1.0f / E);
    float var  = sq * (1.0f / E) - mu * mu;
    float rstd = rsqrtf(var + LN_EPS);

    float4 v = sums4[(size_t)m * (E / 4) + n4];
    float4 g = gamma4[n4];
    float4 b = beta4[n4];
    float4 y;
    y.x = (v.x - mu) * rstd * g.x + b.x;
    y.y = (v.y - mu) * rstd * g.y + b.y;
    y.z = (v.z - mu) * rstd * g.z + b.z;
    y.w = (v.w - mu) * rstd * g.w + b.w;
    if (RELU) {
        y.x = fmaxf(y.x, 0.f); y.y = fmaxf(y.y, 0.f);
        y.z = fmaxf(y.z, 0.f); y.w = fmaxf(y.w, 0.f);
    }
    if (DUP) {
        int n = 4 * n4;
        out_dup[(size_t)(n + 0) * M16 + m] = dup_pack(y.x);
        out_dup[(size_t)(n + 1) * M16 + m] = dup_pack(y.y);
        out_dup[(size_t)(n + 2) * M16 + m] = dup_pack(y.z);
        out_dup[(size_t)(n + 3) * M16 + m] = dup_pack(y.w);
    } else {
        out4[(size_t)m * (E / 4) + n4] = y;
    }
}

// ============================================================
// launcher — 7 launches
// ============================================================
extern "C" void kernel_launch(void* const* d_in, const int* in_sizes, int n_in,
                              void* d_out, int out_size)
{
    const float* emb = (const float*)d_in[0];
    const float* W1  = (const float*)d_in[1];
    const float* b1  = (const float*)d_in[2];
    const float* g1  = (const float*)d_in[3];
    const float* be1 = (const float*)d_in[4];
    const float* W2  = (const float*)d_in[5];
    const float* b2  = (const float*)d_in[6];
    const float* g2  = (const float*)d_in[7];
    const float* be2 = (const float*)d_in[8];
    const int*   bp  = (const int*)d_in[9];

    float* out = (float*)d_out;
    float* out_joint = out;                      // [17][4096]
    float* out_bone  = out + (size_t)J * E;      // [16][4096]

    ull*    h_dup_p;   cudaGetSymbolAddress((void**)&h_dup_p, d_h_dup);
    float*  partial_p; cudaGetSymbolAddress((void**)&partial_p, d_partial);
    float*  sums_p;    cudaGetSymbolAddress((void**)&sums_p, d_sums);
    float2* stats_p;   cudaGetSymbolAddress((void**)&stats_p, d_stats);

    // 1. L2-normalize joints -> output (also gather source for GEMM1)
    normalize_kernel<<<J, 256>>>(emb, out_joint);

    // 2. GEMM1 split-K (gather fused into smem fill)
    gemm_splitk<TK1, true><<<dim3(4, K1 / TK1), 256>>>(
        W1, out_joint, bp, nullptr, partial_p);

    // 3-4. reduce + bias -> sums/stats; apply LN+ReLU -> h dup-transposed
    splitk_reduce_kernel<<<dim3(4, M16), 256>>>(
        (const float4*)partial_p, (const float4*)b1, (float4*)sums_p, stats_p);
    apply_ln_kernel<true, true><<<dim3(4, M16), 256>>>(
        (const float4*)sums_p, stats_p, (const float4*)g1, (const float4*)be1,
        nullptr, h_dup_p);

    // 5. GEMM2 split-K
    gemm_splitk<TK2, false><<<dim3(4, K2 / TK2), 256>>>(
        W2, nullptr, nullptr, h_dup_p, partial_p);

    // 6-7. reduce + bias; apply LN -> final bone features
    splitk_reduce_kernel<<<dim3(4, M16), 256>>>(
        (const float4*)partial_p, (const float4*)b2, (float4*)sums_p, stats_p);
    apply_ln_kernel<false, false><<<dim3(4, M16), 256>>>(
        (const float4*)sums_p, stats_p, (const float4*)g2, (const float4*)be2,
        (float4*)out_bone, nullptr);
}

// round 5
// speedup vs baseline: 2.9072x; 1.0280x over previous
#include <cuda_runtime.h>
#include <cstdint>

#define J   17
#define E   4096
#define M16 16
#define K1  (2*E)       // 8192
#define K2  E           // 4096
#define TK1 128         // GEMM1 K-slab -> 64 slabs
#define TK2 64          // GEMM2 K-slab -> 64 slabs
#define KS  64          // both GEMMs produce 64 K-slabs
#define LN_EPS 1e-5f

typedef unsigned long long ull;

// -------- device scratch --------
__device__ float  d_h[M16 * E];             // 256 KB hidden (linear, coalesced)
__device__ float  d_partial[KS * M16 * E];  // 16 MB
__device__ float  d_sums[M16 * E];          // 256 KB
__device__ float2 d_stats[M16 * 4];         // per-(row,chunk) sum/sumsq

__device__ __forceinline__ void fma2(ull& d, ull a, ull b) {
    asm("fma.rn.f32x2 %0, %1, %2, %0;" : "+l"(d) : "l"(a), "l"(b));
}
__device__ __forceinline__ ull dup_pack(float p) {
    unsigned int u = __float_as_uint(p);
    return ((ull)u << 32) | (ull)u;
}

// ============================================================
// L2-normalize joints, scale by sqrt(E)=64. grid=17, block=256.
// ============================================================
__global__ void __launch_bounds__(256) normalize_kernel(
    const float* __restrict__ x, float* __restrict__ out_joint)
{
    int row = blockIdx.x;
    int tid = threadIdx.x;
    const float* xr = x + (size_t)row * E;

    float s = 0.f;
    float v[E / 256];
    #pragma unroll
    for (int i = 0; i < E / 256; i++) {
        v[i] = xr[tid + i * 256];
        s += v[i] * v[i];
    }
    __shared__ float red[256];
    red[tid] = s;
    __syncthreads();
    for (int off = 128; off > 0; off >>= 1) {
        if (tid < off) red[tid] += red[tid + off];
        __syncthreads();
    }
    __shared__ float s_inv;
    if (tid == 0) s_inv = 64.0f / fmaxf(sqrtf(red[0]), 1e-12f);
    __syncthreads();
    float inv = s_inv;
    #pragma unroll
    for (int i = 0; i < E / 256; i++)
        out_joint[(size_t)row * E + tid + i * 256] = v[i] * inv;
}

// ============================================================
// Split-K GEMM, 4 cols/thread, 2 CTAs/SM.
// out[m][n] = sum_k act[k][m] * W[k][n]
// grid=(4, K/TK), block=256.
// MODE 0: gather pair activations from joint+bone_pairs (GEMM1)
// MODE 1: gather hidden activations from linear h (GEMM2)
// ============================================================
template<int TK, int MODE>
__global__ void __launch_bounds__(256, 2) gemm_splitk(
    const float* __restrict__ W,
    const float* __restrict__ act,     // joint (MODE 0) or h (MODE 1)
    const int*   __restrict__ bp,
    float* __restrict__ partial)
{
    __shared__ ull sp[TK * M16];

    int tid = threadIdx.x;
    int k0 = blockIdx.y * TK;

    {
        int m = tid & 15;
        const float* r0;
        const float* r1;
        if (MODE == 0) {
            r0 = act + (size_t)bp[2 * m] * E;
            r1 = act + (size_t)bp[2 * m + 1] * E;
        } else {
            r0 = act + (size_t)m * E;
            r1 = r0;
        }
        #pragma unroll
        for (int i = 0; i < (TK * M16) / 256; i++) {
            int kl = (tid >> 4) + i * 16;
            int k = k0 + kl;
            float p;
            if (MODE == 0) {
                int col = k & (E - 1);
                p = (k < E) ? r0[col] : r1[col];
            } else {
                p = r0[k];
            }
            sp[kl * M16 + m] = dup_pack(p);
        }
    }
    __syncthreads();

    int n = blockIdx.x * 1024 + tid * 4;
    const float* wp = W + (size_t)k0 * E + n;

    ull acc[M16][2];
    #pragma unroll
    for (int m = 0; m < M16; m++) { acc[m][0] = 0ULL; acc[m][1] = 0ULL; }

    ulonglong2 wv0[4], wv1[4];

    #pragma unroll
    for (int j = 0; j < 4; j++)
        wv0[j] = *reinterpret_cast<const ulonglong2*>(wp + (size_t)j * E);

    #define CONSUME(WV, KB)                                                   \
        _Pragma("unroll")                                                     \
        for (int j = 0; j < 4; j++) {                                         \
            const ulonglong2* row =                                           \
                reinterpret_cast<const ulonglong2*>(sp + ((KB) + j) * M16);   \
            _Pragma("unroll")                                                 \
            for (int q = 0; q < 8; q++) {                                     \
                ulonglong2 r = row[q];                                        \
                fma2(acc[2*q  ][0], WV[j].x, r.x);                            \
                fma2(acc[2*q  ][1], WV[j].y, r.x);                            \
                fma2(acc[2*q+1][0], WV[j].x, r.y);                            \
                fma2(acc[2*q+1][1], WV[j].y, r.y);                            \
            }                                                                 \
        }

    #pragma unroll 1
    for (int cb = 0; cb < TK - 8; cb += 8) {
        #pragma unroll
        for (int j = 0; j < 4; j++)
            wv1[j] = *reinterpret_cast<const ulonglong2*>(wp + (size_t)(cb + 4 + j) * E);
        CONSUME(wv0, cb)
        #pragma unroll
        for (int j = 0; j < 4; j++)
            wv0[j] = *reinterpret_cast<const ulonglong2*>(wp + (size_t)(cb + 8 + j) * E);
        CONSUME(wv1, cb + 4)
    }
    {
        const int cb = TK - 8;
        #pragma unroll
        for (int j = 0; j < 4; j++)
            wv1[j] = *reinterpret_cast<const ulonglong2*>(wp + (size_t)(cb + 4 + j) * E);
        CONSUME(wv0, cb)
        CONSUME(wv1, cb + 4)
    }
    #undef CONSUME

    size_t base = ((size_t)blockIdx.y * M16) * E + n;
    #pragma unroll
    for (int m = 0; m < M16; m++) {
        ulonglong2 o; o.x = acc[m][0]; o.y = acc[m][1];
        *reinterpret_cast<ulonglong2*>(&partial[base + (size_t)m * E]) = o;
    }
}

// ============================================================
// Split-K reduce + bias (float4), per-chunk LN stats.
// grid = (4, 16), block=256.
// ============================================================
__global__ void __launch_bounds__(256) splitk_reduce_kernel(
    const float4* __restrict__ partial4,
    const float4* __restrict__ bias4,
    float4* __restrict__ sums4, float2* __restrict__ stats)
{
    int m   = blockIdx.y;
    int tid = threadIdx.x;
    int n4  = blockIdx.x * 256 + tid;

    const float4* p = partial4 + (size_t)m * (E / 4) + n4;
    const size_t stride = (size_t)M16 * (E / 4);

    float4 a[8];
    a[0] = bias4[n4];
    #pragma unroll
    for (int r = 1; r < 8; r++) a[r] = make_float4(0.f, 0.f, 0.f, 0.f);

    #pragma unroll
    for (int ks = 0; ks < KS; ks += 8) {
        #pragma unroll
        for (int r = 0; r < 8; r++) {
            float4 v = p[(size_t)(ks + r) * stride];
            a[r].x += v.x; a[r].y += v.y; a[r].z += v.z; a[r].w += v.w;
        }
    }
    #pragma unroll
    for (int r = 4; r > 0; r >>= 1)
        #pragma unroll
        for (int s = 0; s < r; s++) {
            a[s].x += a[s + r].x; a[s].y += a[s + r].y;
            a[s].z += a[s + r].z; a[s].w += a[s + r].w;
        }
    float4 v = a[0];
    sums4[(size_t)m * (E / 4) + n4] = v;

    __shared__ float rs[256], rq[256];
    rs[tid] = (v.x + v.y) + (v.z + v.w);
    rq[tid] = (v.x * v.x + v.y * v.y) + (v.z * v.z + v.w * v.w);
    __syncthreads();
    for (int off = 128; off > 0; off >>= 1) {
        if (tid < off) { rs[tid] += rs[tid + off]; rq[tid] += rq[tid + off]; }
        __syncthreads();
    }
    if (tid == 0)
        stats[m * 4 + blockIdx.x] = make_float2(rs[0], rq[0]);
}

// ============================================================
// Apply LN (+ReLU), linear coalesced float4 output.
// grid = (4, 16), block=256.
// ============================================================
template<bool RELU>
__global__ void __launch_bounds__(256) apply_ln_kernel(
    const float4* __restrict__ sums4,
    const float2* __restrict__ stats,
    const float4* __restrict__ gamma4,
    const float4* __restrict__ beta4,
    float4* __restrict__ out4)
{
    int m  = blockIdx.y;
    int n4 = blockIdx.x * 256 + threadIdx.x;

    float2 s0 = stats[m * 4 + 0];
    float2 s1 = stats[m * 4 + 1];
    float2 s2 = stats[m * 4 + 2];
    float2 s3 = stats[m * 4 + 3];
    float sum = (s0.x + s1.x) + (s2.x + s3.x);
    float sq  = (s0.y + s1.y) + (s2.y + s3.y);
    float mu   = sum * (1.0f / E);
    float var  = sq * (1.0f / E) - mu * mu;
    float rstd = rsqrtf(var + LN_EPS);

    float4 v = sums4[(size_t)m * (E / 4) + n4];
    float4 g = gamma4[n4];
    float4 b = beta4[n4];
    float4 y;
    y.x = (v.x - mu) * rstd * g.x + b.x;
    y.y = (v.y - mu) * rstd * g.y + b.y;
    y.z = (v.z - mu) * rstd * g.z + b.z;
    y.w = (v.w - mu) * rstd * g.w + b.w;
    if (RELU) {
        y.x = fmaxf(y.x, 0.f); y.y = fmaxf(y.y, 0.f);
        y.z = fmaxf(y.z, 0.f); y.w = fmaxf(y.w, 0.f);
    }
    out4[(size_t)m * (E / 4) + n4] = y;
}

// ============================================================
// launcher — 7 launches
// ============================================================
extern "C" void kernel_launch(void* const* d_in, const int* in_sizes, int n_in,
                              void* d_out, int out_size)
{
    const float* emb = (const float*)d_in[0];
    const float* W1  = (const float*)d_in[1];
    const float* b1  = (const float*)d_in[2];
    const float* g1  = (const float*)d_in[3];
    const float* be1 = (const float*)d_in[4];
    const float* W2  = (const float*)d_in[5];
    const float* b2  = (const float*)d_in[6];
    const float* g2  = (const float*)d_in[7];
    const float* be2 = (const float*)d_in[8];
    const int*   bp  = (const int*)d_in[9];

    float* out = (float*)d_out;
    float* out_joint = out;                      // [17][4096]
    float* out_bone  = out + (size_t)J * E;      // [16][4096]

    float*  h_p;       cudaGetSymbolAddress((void**)&h_p, d_h);
    float*  partial_p; cudaGetSymbolAddress((void**)&partial_p, d_partial);
    float*  sums_p;    cudaGetSymbolAddress((void**)&sums_p, d_sums);
    float2* stats_p;   cudaGetSymbolAddress((void**)&stats_p, d_stats);

    // 1. L2-normalize joints -> output (also gather source for GEMM1)
    normalize_kernel<<<J, 256>>>(emb, out_joint);

    // 2. GEMM1 split-K (pair gather fused into smem fill)
    gemm_splitk<TK1, 0><<<dim3(4, K1 / TK1), 256>>>(
        W1, out_joint, bp, partial_p);

    // 3-4. reduce + bias -> sums/stats; apply LN+ReLU -> h (linear)
    splitk_reduce_kernel<<<dim3(4, M16), 256>>>(
        (const float4*)partial_p, (const float4*)b1, (float4*)sums_p, stats_p);
    apply_ln_kernel<true><<<dim3(4, M16), 256>>>(
        (const float4*)sums_p, stats_p, (const float4*)g1, (const float4*)be1,
        (float4*)h_p);

    // 5. GEMM2 split-K (h gather fused into smem fill)
    gemm_splitk<TK2, 1><<<dim3(4, K2 / TK2), 256>>>(
        W2, h_p, nullptr, partial_p);

    // 6-7. reduce + bias; apply LN -> final bone features
    splitk_reduce_kernel<<<dim3(4, M16), 256>>>(
        (const float4*)partial_p, (const float4*)b2, (float4*)sums_p, stats_p);
    apply_ln_kernel<false><<<dim3(4, M16), 256>>>(
        (const float4*)sums_p, stats_p, (const float4*)g2, (const float4*)be2,
        (float4*)out_bone);
}